// round 15
// baseline (speedup 1.0000x reference)
#include <cuda_runtime.h>
#include <cuda_bf16.h>

// SPU activation bounds (RIAI SPU-Trainable), collapsed to elementwise.
//
// Backsubstitution of the diagonal+bias matrices reduces to:
//   al = lw*(lw>0?l:u)+lb ;  au = uw*(uw>0?u:l)+ub
//
// Identities for x<0 with s = 1/(1+e^x), E = 1+e^x:
//   spu(x)  = s - 1 ;  spu'(x) = s*s - s = -e^x / E^2
//
// Crossing-branch search: quad-section, 7 steps x 3 probes = 2^-14 one-sided
// dyadic grid (reference: 20-step bisection, 2^-20). Measured rel_err at
// this grid: 2.83e-7 (3500x under the 1e-3 tolerance).
//
// DIVISION-FREE PROBE: covering test a*(uc-c)+s-1 >= req, multiplied by
// E^2 > 0, becomes E*(A*E + g) + (1-g) >= 0, A = -(1+req), g = 1-(uc-c)
// -> 1 FFMA + 1 MUFU.EX2 (raw asm; log2-domain lo2/q2) + ~6 FMAs per probe.
//
// ROUND-15: 2 elements/thread with the two quad-section chains FUSED into
// one loop (6 independent probes/step) — structural 6-way MUFU ILP that
// ptxas cannot serialize away (the R5 attempt failed because the then-huge
// IEEE-div body forced serialization at regs=39; today's body is tiny).
// 1024 warps, 256 CTAs x 128 threads, float2 loads / float4 store.

__device__ __forceinline__ float fex2(float x) {      // 2^x, one MUFU op
    float y;
    asm("ex2.approx.ftz.f32 %0, %1;" : "=f"(y) : "f"(x));
    return y;
}

__device__ __forceinline__ float frcp(float x) {      // 1/x, one MUFU op
    float y;
    asm("rcp.approx.ftz.f32 %0, %1;" : "=f"(y) : "f"(x));
    return y;
}

#define LOG2E 1.4426950408889634f

__device__ __forceinline__ float fexp(float x) { return fex2(x * LOG2E); }
__device__ __forceinline__ float frcp1p(float ex) { return frcp(1.0f + ex); }

// sigmoid(4*x) = 1/(1+e^{-4x})
__device__ __forceinline__ float fsigmoid4(float x) {
    return frcp1p(fex2(x * (-4.0f * LOG2E)));
}

// spu(x), branchless, any sign.
__device__ __forceinline__ float fspu(float x) {
    float s   = frcp1p(fexp(x));
    float neg = s - 1.0f;
    float pos = x * x - 0.5f;
    return (x >= 0.0f) ? pos : neg;
}

// Tangent line (a,b) at x0, branchless, any sign.
// x0 <= -50: exp underflows -> s=1 -> grad = s*s-s = 0, matching reference.
__device__ __forceinline__ void fspu_tangent(float x0, float& a, float& b) {
    float s  = frcp1p(fexp(x0));
    float ga = s * s - s;
    float fa = s - 1.0f;
    float gp = 2.0f * x0;
    float fp = x0 * x0 - 0.5f;
    a = (x0 >= 0.0f) ? gp : ga;
    b = ((x0 >= 0.0f) ? fp : fa) - a * x0;
}

// Everything per-element EXCEPT the bisection (prologue: compute secant,
// tangents, and the search setup; epilogue: combine). The bisection itself
// is fused across the two elements in the kernel body below.
struct SpuPre {
    float l, u, tl, tu, yl, yu, ea, eb;
    float t1a, t1b, t2a, t2b;
    float uc, req, A, one_m_uc;
    bool negative, positive, crossing;
};

__device__ __forceinline__ SpuPre spu_pre(float l, float u,
                                          float tlr, float tur)
{
    SpuPre p;
    p.l = l; p.u = u;
    p.tl = fsigmoid4(tlr);
    p.tu = fsigmoid4(tur);
    p.yl = fspu(l);
    p.yu = fspu(u);
    p.ea = __fdividef(p.yu - p.yl, u - l + 1e-8f);
    p.eb = p.yl - l * p.ea;
    p.negative = (u <= 0.0f);
    p.positive = (l >= 0.0f);
    p.crossing = !(p.negative || p.positive);
    fspu_tangent(l + (u - l) * p.tl, p.t1a, p.t1b);
    fspu_tangent(l + (u - l) * p.tu, p.t2a, p.t2b);
    p.uc  = p.crossing ? u : 0.0f;
    p.req = p.crossing ? p.yu : -0.5f;   // = fspu(uc), select not transcend.
    p.A   = -1.0f - p.req;
    p.one_m_uc = 1.0f - p.uc;
    return p;
}

__device__ __forceinline__ float2 spu_post(const SpuPre& p, float u_end)
{
    // crossing upper: tangent at interp(l, u_end, tu); secant fallback
    float ua, ub_;
    fspu_tangent(p.l + (u_end - p.l) * p.tu, ua, ub_);
    bool not_cov = (ua * p.uc + ub_) <= p.req;
    float cr_uw = not_cov ? p.ea : ua;
    float cr_ub = not_cov ? p.eb : ub_;

    // crossing lower: T1 tangent if tl >= threshold, else steep line @ -0.5
    float den = p.uc - p.l;
    float threshold = __fdividef(-p.l, (den == 0.0f) ? 1.0f : den);
    bool is_normal = (p.tl >= threshold);

    bool  l_norm = (p.l <= -1e-5f) || (p.l > 0.0f);
    float steep  = l_norm ? __fdividef(p.yl + 0.5f, p.l) : -0.25f;

    float safe_thr = (threshold == 0.0f) ? 1.0f : threshold;
    float r  = __fdividef(p.tl, safe_thr);
    float wa = steep * (1.0f - r * r);

    float cr_lw = is_normal ? p.t1a : wa;
    float cr_lb = is_normal ? p.t1b : -0.5f;

    float lw = p.negative ? p.ea  : (p.positive ? p.t1a : cr_lw);
    float lb = p.negative ? p.eb  : (p.positive ? p.t1b : cr_lb);
    float uw = p.negative ? p.t2a : (p.positive ? p.ea  : cr_uw);
    float ub = p.negative ? p.t2b : (p.positive ? p.eb  : cr_ub);

    float al = lw * ((lw > 0.0f) ? p.l : p.u) + lb;
    float au = uw * ((uw > 0.0f) ? p.u : p.l) + ub;
    return make_float2(al, au);
}

__global__ void __launch_bounds__(128)
spu_bounds_kernel(const float2* __restrict__ l_in,
                  const float2* __restrict__ u_in,
                  const float2* __restrict__ tl_raw,
                  const float2* __restrict__ tu_raw,
                  float4* __restrict__ out,
                  int n_pairs)
{
    int i = blockIdx.x * blockDim.x + threadIdx.x;
    if (i >= n_pairs) return;

    float2 l2  = l_in[i];
    float2 u2  = u_in[i];
    float2 tl2 = tl_raw[i];
    float2 tu2 = tu_raw[i];

    SpuPre pa = spu_pre(l2.x, u2.x, tl2.x, tu2.x);
    SpuPre pb = spu_pre(l2.y, u2.y, tl2.y, tu2.y);

    // ---- FUSED quad-section: both elements' searches in one loop.
    // 6 independent probes per step -> structural MUFU ILP.
    float loa  = pa.l,  wA  = -pa.l;
    float loa2 = pa.l * LOG2E, wA2 = -pa.l * LOG2E;
    float lob  = pb.l,  wB  = -pb.l;
    float lob2 = pb.l * LOG2E, wB2 = -pb.l * LOG2E;

    #pragma unroll
    for (int it = 0; it < 7; ++it) {      // 4^7 = 2^-14 grid
        float qa  = 0.25f * wA,  qa2 = 0.25f * wA2;
        float qb  = 0.25f * wB,  qb2 = 0.25f * wB2;
        float Ga  = pa.one_m_uc + loa;    // g_m = G + m*q
        float Gb  = pb.one_m_uc + lob;

        float ka = 0.0f, kb = 0.0f;
        #pragma unroll
        for (int m = 1; m <= 3; ++m) {
            float fm = (float)m;
            // element A probe
            float eA = fex2(fmaf(fm, qa2, loa2));
            float EA = eA + 1.0f;
            float gA = fmaf(fm, qa, Ga);
            float vA = fmaf(EA, fmaf(pa.A, EA, gA), 1.0f - gA);
            ka += (vA >= 0.0f) ? 1.0f : 0.0f;
            // element B probe (independent)
            float eB = fex2(fmaf(fm, qb2, lob2));
            float EB = eB + 1.0f;
            float gB = fmaf(fm, qb, Gb);
            float vB = fmaf(EB, fmaf(pb.A, EB, gB), 1.0f - gB);
            kb += (vB >= 0.0f) ? 1.0f : 0.0f;
        }
        loa  = fmaf(ka, qa,  loa);
        loa2 = fmaf(ka, qa2, loa2);
        wA   = qa;  wA2 = qa2;
        lob  = fmaf(kb, qb,  lob);
        lob2 = fmaf(kb, qb2, lob2);
        wB   = qb;  wB2 = qb2;
    }

    float2 r0 = spu_post(pa, loa);
    float2 r1 = spu_post(pb, lob);

    out[i] = make_float4(r0.x, r0.y, r1.x, r1.y);
}

extern "C" void kernel_launch(void* const* d_in, const int* in_sizes, int n_in,
                              void* d_out, int out_size)
{
    const float2* l  = (const float2*)d_in[0];
    const float2* u  = (const float2*)d_in[1];
    const float2* tl = (const float2*)d_in[2];
    const float2* tu = (const float2*)d_in[3];
    float4* out = (float4*)d_out;

    int n = in_sizes[0];               // 65536 elements (even)
    int n_pairs = n >> 1;              // 32768 threads
    const int threads = 128;
    int blocks = (n_pairs + threads - 1) / threads;   // 256 CTAs
    spu_bounds_kernel<<<blocks, threads>>>(l, u, tl, tu, out, n_pairs);
}

// round 16
// speedup vs baseline: 1.2696x; 1.2696x over previous
#include <cuda_runtime.h>
#include <cuda_bf16.h>

// SPU activation bounds (RIAI SPU-Trainable), collapsed to elementwise.
// FINAL — byte-identical to the session's best measured kernel (R12):
// wall 6.592us, ncu 4.99us, rel_err 2.83e-7.
//
// Backsubstitution of the diagonal+bias matrices reduces to:
//   al = lw*(lw>0?l:u)+lb ;  au = uw*(uw>0?u:l)+ub
//
// Identities for x<0 with s = 1/(1+e^x), E = 1+e^x:
//   spu(x)  = s - 1
//   spu'(x) = s*s - s = -e^x / E^2
//
// Crossing-branch search: largest c in [l,0] whose tangent covers
// (u, spu(u)). Reference: 20-step bisection (2^-20 one-sided dyadic grid).
// Here: quad-section, 7 steps x 3 probes = 2^-14 grid, same one-sided
// property. Measured rel_err at this grid: 2.83e-7 (3500x under tolerance).
//
// DIVISION-FREE PROBE: covering test a*(uc-c) + s - 1 >= req, multiplied by
// E^2 > 0, becomes the polynomial sign test
//     E*(A*E + g) + (1 - g) >= 0,   A = -(1+req), g = 1 - (uc - c)
// -> 1 FFMA + 1 MUFU.EX2 (raw asm, exponent via log2-domain lo2/q2) + ~6
// FMA-class ops per probe. No RCP in the loop.
//
// Session-measured conclusions (all verified by intervention):
//  - plain '/' (IEEE seq) -> __fdividef / rcp.approx: biggest win (-3.5us)
//  - libm exp2f is a ~20-inst software poly; ex2.approx asm is mandatory
//  - below ~340 in-loop insts the kernel is launch-floor-bound; 7 steps is
//    the accuracy-optimal point on the flat part of the time curve
//  - 128thr x 512 CTAs beats 64x1024, 256x256, and both 2-elem/thread
//    variants (ptxas serializes multi-element chains to save registers —
//    reproduced twice at regs=39 and regs=32)
//  - wall run-to-run noise on identical code: +-0.25us

__device__ __forceinline__ float fex2(float x) {      // 2^x, one MUFU op
    float y;
    asm("ex2.approx.ftz.f32 %0, %1;" : "=f"(y) : "f"(x));
    return y;
}

__device__ __forceinline__ float frcp(float x) {      // 1/x, one MUFU op
    float y;
    asm("rcp.approx.ftz.f32 %0, %1;" : "=f"(y) : "f"(x));
    return y;
}

#define LOG2E 1.4426950408889634f

// e^x via single EX2 (caller supplies natural-log argument)
__device__ __forceinline__ float fexp(float x) {
    return fex2(x * LOG2E);
}

__device__ __forceinline__ float frcp1p(float ex) {   // 1/(1+ex)
    return frcp(1.0f + ex);
}

// sigmoid(4*x) = 1/(1+e^{-4x}), exponent folded to one FMUL
__device__ __forceinline__ float fsigmoid4(float x) {
    return frcp1p(fex2(x * (-4.0f * LOG2E)));
}

// spu(x), branchless, any sign.
__device__ __forceinline__ float fspu(float x) {
    float s   = frcp1p(fexp(x));
    float neg = s - 1.0f;
    float pos = x * x - 0.5f;
    return (x >= 0.0f) ? pos : neg;
}

// Tangent line (a,b) at x0, branchless, any sign.
// x0 <= -50: exp underflows -> s=1 -> grad = s*s-s = 0, matching reference.
__device__ __forceinline__ void fspu_tangent(float x0, float& a, float& b) {
    float s  = frcp1p(fexp(x0));
    float ga = s * s - s;            // grad, x0 < 0
    float fa = s - 1.0f;             // spu,  x0 < 0
    float gp = 2.0f * x0;            // grad, x0 >= 0
    float fp = x0 * x0 - 0.5f;       // spu,  x0 >= 0
    a = (x0 >= 0.0f) ? gp : ga;
    b = ((x0 >= 0.0f) ? fp : fa) - a * x0;
}

__global__ void __launch_bounds__(128)
spu_bounds_kernel(const float* __restrict__ l_in,
                  const float* __restrict__ u_in,
                  const float* __restrict__ tl_raw,
                  const float* __restrict__ tu_raw,
                  float2* __restrict__ out,
                  int n_total)
{
    int i = blockIdx.x * blockDim.x + threadIdx.x;
    if (i >= n_total) return;

    float l = l_in[i];
    float u = u_in[i];
    float tl = fsigmoid4(tl_raw[i]);
    float tu = fsigmoid4(tu_raw[i]);

    float yl = fspu(l);
    float yu = fspu(u);

    // secant (endpoint) line
    float ea = __fdividef(yu - yl, u - l + 1e-8f);
    float eb = yl - l * ea;

    bool negative = (u <= 0.0f);
    bool positive = (l >= 0.0f);
    bool crossing = !(negative || positive);

    // T1: tangent at interp(l,u,tl) — positive lower / crossing-normal lower
    float t1a, t1b;
    fspu_tangent(l + (u - l) * tl, t1a, t1b);
    // T2: tangent at interp(l,u,tu) — negative upper
    float t2a, t2b;
    fspu_tangent(l + (u - l) * tu, t2a, t2b);

    // ---- crossing search on [l, 0], uc = crossing ? u : 0 (ref's masking)
    float uc  = crossing ? u : 0.0f;
    float req = crossing ? yu : -0.5f;    // = fspu(uc), no transcendental
    float A   = -1.0f - req;              // poly coefficient
    float one_m_uc = 1.0f - uc;

    float lo  = l;
    float w   = -l;
    float lo2 = l  * LOG2E;               // log2-domain mirror of lo
    float w2  = -l * LOG2E;

    #pragma unroll
    for (int it = 0; it < 7; ++it) {      // 4^7 = 2^-14 grid (see header)
        float q  = 0.25f * w;
        float q2 = 0.25f * w2;
        float G  = one_m_uc + lo;         // g_m = G + m*q

        float k = 0.0f;
        #pragma unroll
        for (int m = 1; m <= 3; ++m) {
            float fm = (float)m;
            float e  = fex2(fmaf(fm, q2, lo2));    // e^{lo + m q}  (1 MUFU)
            float E  = e + 1.0f;
            float g  = fmaf(fm, q, G);             // 1 - (uc - c)
            // sign test:  E*(A*E + g) + (1 - g) >= 0  <=>  tangent covers
            float v  = fmaf(E, fmaf(A, E, g), 1.0f - g);
            k += (v >= 0.0f) ? 1.0f : 0.0f;
        }
        lo  = fmaf(k, q,  lo);
        lo2 = fmaf(k, q2, lo2);
        w   = q;
        w2  = q2;
    }
    float u_end = lo;

    // crossing upper: tangent at interp(l, u_end, tu); secant fallback
    float ua, ub_;
    fspu_tangent(l + (u_end - l) * tu, ua, ub_);
    bool not_cov = (ua * uc + ub_) <= req;
    float cr_uw = not_cov ? ea : ua;
    float cr_ub = not_cov ? eb : ub_;

    // crossing lower: T1 tangent if tl >= threshold, else steep line @ -0.5
    float den = uc - l;
    float threshold = __fdividef(-l, (den == 0.0f) ? 1.0f : den);
    bool is_normal = (tl >= threshold);

    // steep = (spu(l)+0.5)/l for "normal" l (l<=-1e-5 or l>0), else -0.25
    bool  l_norm = (l <= -1e-5f) || (l > 0.0f);
    float steep  = l_norm ? __fdividef(yl + 0.5f, l) : -0.25f;

    float safe_thr = (threshold == 0.0f) ? 1.0f : threshold;
    float r  = __fdividef(tl, safe_thr);
    float wa = steep * (1.0f - r * r);

    float cr_lw = is_normal ? t1a : wa;
    float cr_lb = is_normal ? t1b : -0.5f;

    // ---- combine (exactly one of negative/positive/crossing true)
    float lw = negative ? ea  : (positive ? t1a : cr_lw);
    float lb = negative ? eb  : (positive ? t1b : cr_lb);
    float uw = negative ? t2a : (positive ? ea  : cr_uw);
    float ub = negative ? t2b : (positive ? eb  : cr_ub);

    // diagonal backsubstitution
    float al = lw * ((lw > 0.0f) ? l : u) + lb;
    float au = uw * ((uw > 0.0f) ? u : l) + ub;

    out[i] = make_float2(al, au);
}

extern "C" void kernel_launch(void* const* d_in, const int* in_sizes, int n_in,
                              void* d_out, int out_size)
{
    const float* l  = (const float*)d_in[0];
    const float* u  = (const float*)d_in[1];
    const float* tl = (const float*)d_in[2];
    const float* tu = (const float*)d_in[3];
    float2* out = (float2*)d_out;

    int n = in_sizes[0];               // 64 * 1024 = 65536 elements
    const int threads = 128;           // measured optimum (R12: 6.592us)
    int blocks = (n + threads - 1) / threads;   // 512 CTAs, single wave
    spu_bounds_kernel<<<blocks, threads>>>(l, u, tl, tu, out, n);
}